// round 4
// baseline (speedup 1.0000x reference)
#include <cuda_runtime.h>
#include <cstdint>

#define NV 100000
#define NE 800000
#define D  256

// Scratch (allocation-free: __device__ globals).
__device__ __align__(16) float g_aggr[(size_t)NV * D];
__device__ unsigned g_cnt[NV];     // per-vertex edge count
__device__ unsigned g_off[NV];     // CSR start offsets
__device__ unsigned g_cur[NV];     // fill cursors
__device__ int      g_eid[NE];     // edge ids grouped by receiver
__device__ int      g_idx_is64;    // edge_index dtype flag

// ---------------------------------------------------------------------------
// Kernel 0: detect edge_index dtype (int64 vs silently-int32 from JAX).
// Indices < 2^17, so genuine int64 has all-zero high words.
// ---------------------------------------------------------------------------
__global__ void detect_idx_kernel(const int* __restrict__ idx_raw) {
    int is64 = 1;
#pragma unroll 1
    for (int i = 0; i < 64; i++)
        if (idx_raw[2 * i + 1] != 0) { is64 = 0; break; }
    g_idx_is64 = is64;
}

__device__ __forceinline__ int load_recv(const void* eidx_raw, int e) {
    if (g_idx_is64) return (int)((const long long*)eidx_raw)[NE + e];
    return ((const int*)eidx_raw)[NE + e];
}

// ---------------------------------------------------------------------------
// CSR build: zero counts -> histogram -> prefix scan -> fill edge lists
// ---------------------------------------------------------------------------
__global__ void zero_cnt_kernel() {
    int i = blockIdx.x * 256 + threadIdx.x;
    if (i < NV) g_cnt[i] = 0;
}

__global__ void hist_kernel(const void* __restrict__ eidx_raw) {
    int e = blockIdx.x * 256 + threadIdx.x;     // 3125 x 256 = 800000 exact
    int r = load_recv(eidx_raw, e);
    if (r >= 0 && r < NV) atomicAdd(&g_cnt[r], 1u);
}

// Single-block exclusive scan over 100K counts (1024 threads x 98 items).
__global__ void scan_kernel() {
    __shared__ unsigned part[1024];
    const int t = threadIdx.x;
    const int CH = (NV + 1023) / 1024;          // 98
    const int base = t * CH;
    unsigned s = 0;
    for (int i = 0; i < CH; i++) {
        int idx = base + i;
        if (idx < NV) s += g_cnt[idx];
    }
    part[t] = s;
    __syncthreads();
    for (int off = 1; off < 1024; off <<= 1) {  // Hillis-Steele inclusive scan
        unsigned add = (t >= off) ? part[t - off] : 0u;
        __syncthreads();
        part[t] += add;
        __syncthreads();
    }
    unsigned run = (t == 0) ? 0u : part[t - 1];
    for (int i = 0; i < CH; i++) {
        int idx = base + i;
        if (idx < NV) {
            g_off[idx] = run;
            g_cur[idx] = run;
            run += g_cnt[idx];
        }
    }
}

__global__ void fill_kernel(const void* __restrict__ eidx_raw) {
    int e = blockIdx.x * 256 + threadIdx.x;
    int r = load_recv(eidx_raw, e);
    if (r >= 0 && r < NV) {
        unsigned p = atomicAdd(&g_cur[r], 1u);
        g_eid[p] = e;
    }
}

// ---------------------------------------------------------------------------
// Gather-sum: one warp per vertex. Streams each edge row once (819 MB total),
// coalesced float4 reads, register accumulation, no fp atomics.
// ---------------------------------------------------------------------------
__global__ void gather_kernel(const float* __restrict__ efeat) {
    int v    = blockIdx.x * 8 + (threadIdx.x >> 5);   // 12500 x 8 = 100000 exact
    int lane = threadIdx.x & 31;
    unsigned start = g_off[v];
    unsigned deg   = g_cnt[v];

    float4 a0 = make_float4(0.f, 0.f, 0.f, 0.f);
    float4 a1 = make_float4(0.f, 0.f, 0.f, 0.f);

    unsigned i = 0;
    for (; i + 2 <= deg; i += 2) {                    // 2-way ILP on row fetch
        int e0 = g_eid[start + i];
        int e1 = g_eid[start + i + 1];
        const float4* s0 = (const float4*)(efeat + (size_t)e0 * D);
        const float4* s1 = (const float4*)(efeat + (size_t)e1 * D);
        float4 b0 = __ldg(s0 + lane), b1 = __ldg(s0 + lane + 32);
        float4 c0 = __ldg(s1 + lane), c1 = __ldg(s1 + lane + 32);
        a0.x += b0.x; a0.y += b0.y; a0.z += b0.z; a0.w += b0.w;
        a1.x += b1.x; a1.y += b1.y; a1.z += b1.z; a1.w += b1.w;
        a0.x += c0.x; a0.y += c0.y; a0.z += c0.z; a0.w += c0.w;
        a1.x += c1.x; a1.y += c1.y; a1.z += c1.z; a1.w += c1.w;
    }
    if (i < deg) {
        int e0 = g_eid[start + i];
        const float4* s0 = (const float4*)(efeat + (size_t)e0 * D);
        float4 b0 = __ldg(s0 + lane), b1 = __ldg(s0 + lane + 32);
        a0.x += b0.x; a0.y += b0.y; a0.z += b0.z; a0.w += b0.w;
        a1.x += b1.x; a1.y += b1.y; a1.z += b1.z; a1.w += b1.w;
    }

    float4* dst = (float4*)(g_aggr + (size_t)v * D);
    dst[lane]      = a0;
    dst[lane + 32] = a1;
}

// ---------------------------------------------------------------------------
// Kernel: fused 3-layer MLP on [vertex | aggr]  (K=512 -> 256 -> 256)
// CTA tile: 64 rows x 256 cols. 256 threads, 8x8 outputs/thread.
// Accumulators in packed f32x2 (fma.rn.f32x2: 2 FMA per fp-pipe issue).
// (unchanged from R2 — known-correct; tcgen05 rewrite is next round)
// ---------------------------------------------------------------------------
#define BM   64
#define BK   16
#define XPAD 20
#define SMEM_FLOATS (BM * D + BM * XPAD + BK * D)
#define SMEM_BYTES  (SMEM_FLOATS * 4)

__device__ __forceinline__ unsigned long long pack2(float x) {
    unsigned long long r; unsigned u = __float_as_uint(x);
    asm("mov.b64 %0, {%1, %1};" : "=l"(r) : "r"(u));
    return r;
}
#define FMA2(d, a, b) asm("fma.rn.f32x2 %0, %1, %2, %0;" : "+l"(d) : "l"(a), "l"(b))

__device__ __forceinline__ void unpack2(unsigned long long v, float& lo, float& hi) {
    unsigned a, b;
    asm("mov.b64 {%0, %1}, %2;" : "=r"(a), "=r"(b) : "l"(v));
    lo = __uint_as_float(a); hi = __uint_as_float(b);
}

__global__ __launch_bounds__(256, 2)
void mlp_kernel(const float* __restrict__ vfeat,
                const float* __restrict__ W1, const float* __restrict__ b1,
                const float* __restrict__ W2, const float* __restrict__ b2,
                const float* __restrict__ W3, const float* __restrict__ b3,
                float* __restrict__ out)
{
    extern __shared__ float sm[];
    float* h_buf = sm;                   // BM * D
    float* Xs    = h_buf + BM * D;       // BM * XPAD
    float* Ws    = Xs + BM * XPAD;       // BK * D

    const int tid  = threadIdx.x;
    const int tcol = tid & 31;
    const int trow = tid >> 5;
    const int row0 = blockIdx.x * BM;

    unsigned long long acc[8][4];

#pragma unroll
    for (int i = 0; i < 8; i++)
#pragma unroll
        for (int j = 0; j < 4; j++) acc[i][j] = 0ULL;

    for (int k0 = 0; k0 < 2 * D; k0 += BK) {
        const float* src = (k0 < D) ? (vfeat  + (size_t)row0 * D + k0)
                                    : (g_aggr + (size_t)row0 * D + (k0 - D));
        {
            int r  = tid >> 2;
            int c4 = (tid & 3) * 4;
            float4 v = make_float4(0.f, 0.f, 0.f, 0.f);
            if (row0 + r < NV) v = *(const float4*)(src + (size_t)r * D + c4);
            *(float4*)(Xs + r * XPAD + c4) = v;
        }
        {
            const float4* wsrc = (const float4*)(W1 + (size_t)k0 * D);
            float4* wdst = (float4*)Ws;
#pragma unroll
            for (int i = 0; i < 4; i++) wdst[tid + i * 256] = wsrc[tid + i * 256];
        }
        __syncthreads();
#pragma unroll
        for (int kk = 0; kk < BK; kk++) {
            const float* wrow = Ws + kk * D + tcol * 8;
            ulonglong2 q0 = *(const ulonglong2*)wrow;
            ulonglong2 q1 = *(const ulonglong2*)(wrow + 4);
            unsigned long long bb[4] = {q0.x, q0.y, q1.x, q1.y};
#pragma unroll
            for (int i = 0; i < 8; i++) {
                unsigned long long a2 = pack2(Xs[(trow * 8 + i) * XPAD + kk]);
#pragma unroll
                for (int j = 0; j < 4; j++) FMA2(acc[i][j], a2, bb[j]);
            }
        }
        __syncthreads();
    }
    {
        float4 bv0 = *(const float4*)(b1 + tcol * 8);
        float4 bv1 = *(const float4*)(b1 + tcol * 8 + 4);
        float bias[8] = {bv0.x, bv0.y, bv0.z, bv0.w, bv1.x, bv1.y, bv1.z, bv1.w};
#pragma unroll
        for (int i = 0; i < 8; i++) {
            float v[8];
#pragma unroll
            for (int j = 0; j < 4; j++) unpack2(acc[i][j], v[2 * j], v[2 * j + 1]);
#pragma unroll
            for (int j = 0; j < 8; j++) v[j] = fmaxf(v[j] + bias[j], 0.f);
            float* dst = h_buf + (trow * 8 + i) * D + tcol * 8;
            *(float4*)dst       = make_float4(v[0], v[1], v[2], v[3]);
            *(float4*)(dst + 4) = make_float4(v[4], v[5], v[6], v[7]);
        }
    }
    __syncthreads();

#pragma unroll 1
    for (int layer = 0; layer < 2; layer++) {
        const float* Wg = (layer == 0) ? W2 : W3;
        const float* bg = (layer == 0) ? b2 : b3;
#pragma unroll
        for (int i = 0; i < 8; i++)
#pragma unroll
            for (int j = 0; j < 4; j++) acc[i][j] = 0ULL;

        for (int k0 = 0; k0 < D; k0 += BK) {
            {
                const float4* wsrc = (const float4*)(Wg + (size_t)k0 * D);
                float4* wdst = (float4*)Ws;
#pragma unroll
                for (int i = 0; i < 4; i++) wdst[tid + i * 256] = wsrc[tid + i * 256];
            }
            __syncthreads();
#pragma unroll
            for (int kk = 0; kk < BK; kk++) {
                const float* wrow = Ws + kk * D + tcol * 8;
                ulonglong2 q0 = *(const ulonglong2*)wrow;
                ulonglong2 q1 = *(const ulonglong2*)(wrow + 4);
                unsigned long long bb[4] = {q0.x, q0.y, q1.x, q1.y};
#pragma unroll
                for (int i = 0; i < 8; i++) {
                    unsigned long long a2 = pack2(h_buf[(trow * 8 + i) * D + k0 + kk]);
#pragma unroll
                    for (int j = 0; j < 4; j++) FMA2(acc[i][j], a2, bb[j]);
                }
            }
            __syncthreads();
        }

        float4 bv0 = *(const float4*)(bg + tcol * 8);
        float4 bv1 = *(const float4*)(bg + tcol * 8 + 4);
        float bias[8] = {bv0.x, bv0.y, bv0.z, bv0.w, bv1.x, bv1.y, bv1.z, bv1.w};

        if (layer == 0) {
#pragma unroll
            for (int i = 0; i < 8; i++) {
                float v[8];
#pragma unroll
                for (int j = 0; j < 4; j++) unpack2(acc[i][j], v[2 * j], v[2 * j + 1]);
#pragma unroll
                for (int j = 0; j < 8; j++) v[j] = fmaxf(v[j] + bias[j], 0.f);
                float* dst = h_buf + (trow * 8 + i) * D + tcol * 8;
                *(float4*)dst       = make_float4(v[0], v[1], v[2], v[3]);
                *(float4*)(dst + 4) = make_float4(v[4], v[5], v[6], v[7]);
            }
            __syncthreads();
        } else {
#pragma unroll
            for (int i = 0; i < 8; i++) {
                int row = row0 + trow * 8 + i;
                if (row < NV) {
                    float v[8];
#pragma unroll
                    for (int j = 0; j < 4; j++) unpack2(acc[i][j], v[2 * j], v[2 * j + 1]);
#pragma unroll
                    for (int j = 0; j < 8; j++) v[j] += bias[j];
                    float* dst = out + (size_t)row * D + tcol * 8;
                    *(float4*)dst       = make_float4(v[0], v[1], v[2], v[3]);
                    *(float4*)(dst + 4) = make_float4(v[4], v[5], v[6], v[7]);
                }
            }
        }
    }
}

// ---------------------------------------------------------------------------
extern "C" void kernel_launch(void* const* d_in, const int* in_sizes, int n_in,
                              void* d_out, int out_size) {
    const float* vfeat = (const float*)d_in[0];
    const float* efeat = (const float*)d_in[1];
    const void*  eidx  = d_in[2];                        // [2, NE] int64 OR int32
    const float* W1 = (const float*)d_in[3];
    const float* b1 = (const float*)d_in[4];
    const float* W2 = (const float*)d_in[5];
    const float* b2 = (const float*)d_in[6];
    const float* W3 = (const float*)d_in[7];
    const float* b3 = (const float*)d_in[8];
    float* out = (float*)d_out;

    cudaFuncSetAttribute(mlp_kernel, cudaFuncAttributeMaxDynamicSharedMemorySize,
                         SMEM_BYTES);

    detect_idx_kernel<<<1, 1>>>((const int*)eidx);
    zero_cnt_kernel<<<(NV + 255) / 256, 256>>>();
    hist_kernel<<<NE / 256, 256>>>(eidx);
    scan_kernel<<<1, 1024>>>();
    fill_kernel<<<NE / 256, 256>>>(eidx);
    gather_kernel<<<NV / 8, 256>>>(efeat);
    mlp_kernel<<<(NV + BM - 1) / BM, 256, SMEM_BYTES>>>(vfeat, W1, b1, W2, b2,
                                                        W3, b3, out);
}

// round 8
// speedup vs baseline: 1.8700x; 1.8700x over previous
#include <cuda_runtime.h>
#include <cuda_bf16.h>
#include <cstdint>

#define NV 100000
#define NE 800000
#define D  256

// ---------------- device scratch (allocation-free) -------------------------
__device__ __align__(16) float g_aggr[(size_t)NV * D];
__device__ int g_idx_is64;
// W^T split into bf16 hi/lo, 16 chunks of [256 n][64 k]:
// chunks 0-7 = W1 (K=512), 8-11 = W2, 12-15 = W3.
__device__ __align__(16) unsigned short g_Bhi[16][16384];
__device__ __align__(16) unsigned short g_Blo[16][16384];

// ---------------- helpers --------------------------------------------------
__device__ __forceinline__ uint32_t smem_u32(const void* p) {
    uint32_t a;
    asm("{ .reg .u64 t; cvta.to.shared.u64 t, %1; cvt.u32.u64 %0, t; }"
        : "=r"(a) : "l"(p));
    return a;
}
__device__ __forceinline__ void split_bf16(float x, unsigned short& h, unsigned short& l) {
    __nv_bfloat16 hb = __float2bfloat16(x);
    float rem = x - __bfloat162float(hb);
    __nv_bfloat16 lb = __float2bfloat16(rem);
    h = *(unsigned short*)&hb;
    l = *(unsigned short*)&lb;
}
__device__ __forceinline__ void ldm4(unsigned* r, uint32_t addr) {
    asm volatile("ldmatrix.sync.aligned.m8n8.x4.shared.b16 {%0,%1,%2,%3}, [%4];"
                 : "=r"(r[0]), "=r"(r[1]), "=r"(r[2]), "=r"(r[3]) : "r"(addr));
}
__device__ __forceinline__ void mma16816(float* c, const unsigned* a, const unsigned* b) {
    asm volatile("mma.sync.aligned.m16n8k16.row.col.f32.bf16.bf16.f32 "
                 "{%0,%1,%2,%3}, {%4,%5,%6,%7}, {%8,%9}, {%0,%1,%2,%3};"
                 : "+f"(c[0]), "+f"(c[1]), "+f"(c[2]), "+f"(c[3])
                 : "r"(a[0]), "r"(a[1]), "r"(a[2]), "r"(a[3]), "r"(b[0]), "r"(b[1]));
}

// ---------------- detect / zero / atomic scatter (R2, proven) --------------
__global__ void detect_idx_kernel(const int* __restrict__ idx_raw) {
    int is64 = 1;
#pragma unroll 1
    for (int i = 0; i < 64; i++)
        if (idx_raw[2 * i + 1] != 0) { is64 = 0; break; }
    g_idx_is64 = is64;
}

__global__ void zero_aggr_kernel() {
    size_t i = (size_t)blockIdx.x * blockDim.x + threadIdx.x;
    ((float4*)g_aggr)[i] = make_float4(0.f, 0.f, 0.f, 0.f);
}

__global__ void scatter_kernel(const float* __restrict__ efeat,
                               const void* __restrict__ eidx_raw) {
    int e    = blockIdx.x * 8 + (threadIdx.x >> 5);
    int lane = threadIdx.x & 31;
    long long r;
    if (g_idx_is64) r = ((const long long*)eidx_raw)[NE + e];
    else            r = ((const int*)eidx_raw)[NE + e];
    if (r < 0 || r >= NV) return;
    const float4* src = (const float4*)(efeat + (size_t)e * D);
    float* dst = g_aggr + (size_t)r * D;
#pragma unroll
    for (int i = 0; i < 2; i++) {
        int c = lane + i * 32;
        float4 v = src[c];
        asm volatile("red.global.add.v4.f32 [%0], {%1,%2,%3,%4};"
                     :: "l"(dst + c * 4), "f"(v.x), "f"(v.y), "f"(v.z), "f"(v.w)
                     : "memory");
    }
}

// ---------------- weight prep: transpose + hi/lo split ---------------------
__global__ void prep_weights_kernel(const float* __restrict__ W1,
                                    const float* __restrict__ W2,
                                    const float* __restrict__ W3) {
    int chunk = blockIdx.y;                       // 0..15
    int t = blockIdx.x * 256 + threadIdx.x;       // 0..16383
    int n  = t >> 6;                              // 0..255 output col
    int kk = t & 63;                              // 0..63 within chunk
    const float* W; int kbase;
    if (chunk < 8)       { W = W1; kbase = chunk * 64; }
    else if (chunk < 12) { W = W2; kbase = (chunk - 8) * 64; }
    else                 { W = W3; kbase = (chunk - 12) * 64; }
    float w = W[(size_t)(kbase + kk) * 256 + n];
    unsigned short h, l; split_bf16(w, h, l);
    g_Bhi[chunk][n * 64 + kk] = h;
    g_Blo[chunk][n * 64 + kk] = l;
}

// ---------------- mma.sync fused MLP ---------------------------------------
// CTA 128 rows x 256 cols, 512 threads = 16 warps (4x4), warp tile 32x64.
// A smem: [128][264 bf16] hi+lo (full K=256 for layers 2/3; layer1 stages
// 64-col chunks into slots). B smem: [256 n][72 bf16] hi+lo per chunk.
#define ASTRIDE 528     /* 264 bf16 * 2B ; 132 banks = 4 mod 32 -> conflict-free */
#define BSTRIDE 144     /*  72 bf16 * 2B ;  36 banks = 4 mod 32 */
#define OFS_AHI 0
#define OFS_ALO (128 * ASTRIDE)
#define OFS_BHI (2 * 128 * ASTRIDE)
#define OFS_BLO (OFS_BHI + 256 * BSTRIDE)
#define SMEM_TOTAL (OFS_BLO + 256 * BSTRIDE)   /* 208896 B */

__global__ __launch_bounds__(512, 1)
void mlp_mma_kernel(const float* __restrict__ vfeat,
                    const float* __restrict__ b1,
                    const float* __restrict__ b2,
                    const float* __restrict__ b3,
                    float* __restrict__ out)
{
    extern __shared__ char smem[];
    const uint32_t sb = smem_u32(smem);
    const int tid  = threadIdx.x;
    const int lane = tid & 31;
    const int wid  = tid >> 5;
    const int wr0  = (wid >> 2) * 32;            // warp row base 0/32/64/96
    const int wc0  = (wid & 3) * 64;             // warp col base 0/64/128/192
    const int row0 = blockIdx.x * 128;

    // per-lane ldmatrix address components
    const uint32_t aOfs = (uint32_t)(wr0 + (lane & 15)) * ASTRIDE + ((lane >> 4) << 4);
    const uint32_t bOfs = (uint32_t)(wc0 + (lane & 7) + ((lane >> 4) << 3)) * BSTRIDE
                        + (((lane >> 3) & 1) << 4);
    const uint32_t aHi = sb + OFS_AHI + aOfs, aLo = sb + OFS_ALO + aOfs;
    const uint32_t bHi = sb + OFS_BHI + bOfs, bLo = sb + OFS_BLO + bOfs;

    float acc[2][8][4];

#pragma unroll 1
    for (int layer = 0; layer < 3; layer++) {
#pragma unroll
        for (int i = 0; i < 2; i++)
#pragma unroll
            for (int j = 0; j < 8; j++)
#pragma unroll
                for (int q = 0; q < 4; q++) acc[i][j][q] = 0.f;

        const int nchunks = (layer == 0) ? 8 : 4;
#pragma unroll 1
        for (int c = 0; c < nchunks; c++) {
            __syncthreads();                      // prev compute done w/ smem
            if (layer == 0) {                     // stage+split A chunk from gmem
                const float* src = (c < 4) ? (vfeat + c * 64)
                                           : (g_aggr + (c - 4) * 64);
                int r  = tid >> 2;
                int cb = (tid & 3) * 16;
                int slot = c & 3;
                char* ah = smem + OFS_AHI + r * ASTRIDE + (slot * 64 + cb) * 2;
                char* al = smem + OFS_ALO + r * ASTRIDE + (slot * 64 + cb) * 2;
                bool ok = (row0 + r) < NV;
#pragma unroll
                for (int i = 0; i < 4; i++) {
                    float4 v = make_float4(0.f, 0.f, 0.f, 0.f);
                    if (ok) v = *(const float4*)(src + (size_t)(row0 + r) * D + cb + i * 4);
                    unsigned short h0,l0,h1,l1,h2,l2,h3,l3;
                    split_bf16(v.x, h0, l0); split_bf16(v.y, h1, l1);
                    split_bf16(v.z, h2, l2); split_bf16(v.w, h3, l3);
                    *(uint2*)(ah + i * 8) = make_uint2((uint32_t)h0 | ((uint32_t)h1 << 16),
                                                       (uint32_t)h2 | ((uint32_t)h3 << 16));
                    *(uint2*)(al + i * 8) = make_uint2((uint32_t)l0 | ((uint32_t)l1 << 16),
                                                       (uint32_t)l2 | ((uint32_t)l3 << 16));
                }
            }
            {   // stage B chunk (hi+lo): 256n x 64k bf16 = 2048 int4 each
                int img = (layer == 0) ? c : (8 + 4 * (layer - 1) + c);
                const int4* sh = (const int4*)g_Bhi[img];
                const int4* sl = (const int4*)g_Blo[img];
#pragma unroll
                for (int i = 0; i < 4; i++) {     // 4 x 512 = 2048 int4
                    int v = i * 512 + tid;        // int4 index, 0..2047
                    int n  = v >> 3;              // 0..255
                    int kb = (v & 7) * 16;        // byte offset within row
                    *(int4*)(smem + OFS_BHI + n * BSTRIDE + kb) = sh[v];
                    *(int4*)(smem + OFS_BLO + n * BSTRIDE + kb) = sl[v];
                }
            }
            __syncthreads();

            const int colbase = ((layer == 0) ? (c & 3) : c) * 64;
#pragma unroll
            for (int k0 = 0; k0 < 64; k0 += 16) {
                const uint32_t kb = (uint32_t)(colbase + k0) * 2;
                unsigned ah4[2][4], bh4[4][4];
                ldm4(ah4[0], aHi + kb);
                ldm4(ah4[1], aHi + 16 * ASTRIDE + kb);
#pragma unroll
                for (int blk = 0; blk < 4; blk++)
                    ldm4(bh4[blk], bHi + blk * 16 * BSTRIDE + k0 * 2);
#pragma unroll
                for (int i = 0; i < 2; i++)
#pragma unroll
                    for (int j = 0; j < 8; j++)
                        mma16816(acc[i][j], ah4[i], &bh4[j >> 1][(j & 1) * 2]);
                {
                    unsigned bl4[4][4];
#pragma unroll
                    for (int blk = 0; blk < 4; blk++)
                        ldm4(bl4[blk], bLo + blk * 16 * BSTRIDE + k0 * 2);
#pragma unroll
                    for (int i = 0; i < 2; i++)
#pragma unroll
                        for (int j = 0; j < 8; j++)
                            mma16816(acc[i][j], ah4[i], &bl4[j >> 1][(j & 1) * 2]);
                }
                {
                    unsigned al4[2][4];
                    ldm4(al4[0], aLo + kb);
                    ldm4(al4[1], aLo + 16 * ASTRIDE + kb);
#pragma unroll
                    for (int i = 0; i < 2; i++)
#pragma unroll
                        for (int j = 0; j < 8; j++)
                            mma16816(acc[i][j], al4[i], &bh4[j >> 1][(j & 1) * 2]);
                }
            }
        }
        __syncthreads();                          // all warps done reading smem

        // ---- epilogue ----
        const float* bias = (layer == 0) ? b1 : (layer == 1) ? b2 : b3;
        const int rbase = wr0 + (lane >> 2);
        const int cbase = wc0 + (lane & 3) * 2;
        if (layer < 2) {                          // bias+ReLU -> split -> A smem
#pragma unroll
            for (int i = 0; i < 2; i++)
#pragma unroll
                for (int j = 0; j < 8; j++) {
                    int col = cbase + j * 8;
                    float bb0 = bias[col], bb1 = bias[col + 1];
                    float v0 = fmaxf(acc[i][j][0] + bb0, 0.f);
                    float v1 = fmaxf(acc[i][j][1] + bb1, 0.f);
                    float v2 = fmaxf(acc[i][j][2] + bb0, 0.f);
                    float v3 = fmaxf(acc[i][j][3] + bb1, 0.f);
                    int r0 = rbase + i * 16, r1 = r0 + 8;
                    unsigned short h,l, h2,l2;
                    split_bf16(v0, h, l);  split_bf16(v1, h2, l2);
                    *(uint32_t*)(smem + OFS_AHI + r0 * ASTRIDE + col * 2) =
                        (uint32_t)h | ((uint32_t)h2 << 16);
                    *(uint32_t*)(smem + OFS_ALO + r0 * ASTRIDE + col * 2) =
                        (uint32_t)l | ((uint32_t)l2 << 16);
                    split_bf16(v2, h, l);  split_bf16(v3, h2, l2);
                    *(uint32_t*)(smem + OFS_AHI + r1 * ASTRIDE + col * 2) =
                        (uint32_t)h | ((uint32_t)h2 << 16);
                    *(uint32_t*)(smem + OFS_ALO + r1 * ASTRIDE + col * 2) =
                        (uint32_t)l | ((uint32_t)l2 << 16);
                }
            __syncthreads();                      // activations visible
        } else {                                  // final: bias -> gmem
#pragma unroll
            for (int i = 0; i < 2; i++) {
                int r0 = row0 + rbase + i * 16;
#pragma unroll
                for (int j = 0; j < 8; j++) {
                    int col = cbase + j * 8;
                    float bb0 = bias[col], bb1 = bias[col + 1];
                    if (r0 < NV) {
                        float2 v = make_float2(acc[i][j][0] + bb0, acc[i][j][1] + bb1);
                        *(float2*)(out + (size_t)r0 * D + col) = v;
                    }
                    if (r0 + 8 < NV) {
                        float2 v = make_float2(acc[i][j][2] + bb0, acc[i][j][3] + bb1);
                        *(float2*)(out + (size_t)(r0 + 8) * D + col) = v;
                    }
                }
            }
        }
    }
}

// ---------------------------------------------------------------------------
extern "C" void kernel_launch(void* const* d_in, const int* in_sizes, int n_in,
                              void* d_out, int out_size) {
    const float* vfeat = (const float*)d_in[0];
    const float* efeat = (const float*)d_in[1];
    const void*  eidx  = d_in[2];                 // [2, NE] int64 OR int32
    const float* W1 = (const float*)d_in[3];
    const float* b1 = (const float*)d_in[4];
    const float* W2 = (const float*)d_in[5];
    const float* b2 = (const float*)d_in[6];
    const float* W3 = (const float*)d_in[7];
    const float* b3 = (const float*)d_in[8];
    float* out = (float*)d_out;

    cudaFuncSetAttribute(mlp_mma_kernel,
                         cudaFuncAttributeMaxDynamicSharedMemorySize, SMEM_TOTAL);

    detect_idx_kernel<<<1, 1>>>((const int*)eidx);
    zero_aggr_kernel<<<(NV * D / 4) / 256, 256>>>();
    scatter_kernel<<<NE / 8, 256>>>(efeat, eidx);
    prep_weights_kernel<<<dim3(64, 16), 256>>>(W1, W2, W3);
    mlp_mma_kernel<<<(NV + 127) / 128, 512, SMEM_TOTAL>>>(vfeat, b1, b2, b3, out);
}